// round 10
// baseline (speedup 1.0000x reference)
#include <cuda_runtime.h>
#include <cuda_bf16.h>
#include <cstdint>
#include <cstddef>

#define DIM     768
#define HEADS   12
#define HD      64
#define RR      64
#define BB      2
#define NSEQ    4096
#define CHUNK   1024
#define NCHUNKS 4
#define TOKENS  (BB*NSEQ)     // 8192
#define QKV_DIM (3*DIM)       // 2304
#define NEXP    8
#define LSCALE  2.0f          // 128 / 64
#define ATT_SCALE 0.125f      // 64^-0.5
#define LOG2E   1.4426950408889634f

typedef __nv_bfloat16 bf16;

// ------------------------------------------------------------------ scratch
__device__ __align__(16) bf16 g_xh [(size_t)TOKENS * DIM],   g_xl [(size_t)TOKENS * DIM];
__device__ __align__(16) bf16 g_oh [(size_t)TOKENS * DIM],   g_ol [(size_t)TOKENS * DIM];
__device__ __align__(16) bf16 g_wqh[(size_t)QKV_DIM * DIM],  g_wql[(size_t)QKV_DIM * DIM];
__device__ __align__(16) bf16 g_wph[(size_t)DIM * DIM],      g_wpl[(size_t)DIM * DIM];
__device__ __align__(16) bf16 g_bqh[(size_t)NEXP * QKV_DIM * RR], g_bql[(size_t)NEXP * QKV_DIM * RR];
__device__ __align__(16) bf16 g_bph[(size_t)NEXP * DIM * RR],     g_bpl[(size_t)NEXP * DIM * RR];
__device__ __align__(16) bf16 g_aqh[(size_t)NEXP * RR * DIM],     g_aql[(size_t)NEXP * RR * DIM];
__device__ __align__(16) bf16 g_aph[(size_t)NEXP * RR * DIM],     g_apl[(size_t)NEXP * RR * DIM];
__device__ __align__(16) bf16 g_hh [(size_t)TOKENS * RR],    g_hl [(size_t)TOKENS * RR];

__device__ __align__(16) bf16 g_qah[(size_t)BB*HEADS*NSEQ*HD], g_qal[(size_t)BB*HEADS*NSEQ*HD];
__device__ __align__(16) bf16 g_kah[(size_t)BB*HEADS*NSEQ*HD], g_kal[(size_t)BB*HEADS*NSEQ*HD];
__device__ __align__(16) bf16 g_vth[(size_t)BB*HEADS*HD*NSEQ], g_vtl[(size_t)BB*HEADS*HD*NSEQ];

// ------------------------------------------------------------------ helpers
__device__ __forceinline__ float ex2f(float x) {
    float y; asm("ex2.approx.f32 %0, %1;" : "=f"(y) : "f"(x)); return y;
}
__device__ __forceinline__ uint32_t s2u(const void* p) {
    uint32_t a;
    asm("{ .reg .u64 t; cvta.to.shared.u64 t, %1; cvt.u32.u64 %0, t; }" : "=r"(a) : "l"(p));
    return a;
}
__device__ __forceinline__ void cpa16(uint32_t d, const void* s) {
    asm volatile("cp.async.cg.shared.global [%0], [%1], 16;" :: "r"(d), "l"(s));
}
#define CP_COMMIT() asm volatile("cp.async.commit_group;" ::: "memory")
#define CP_WAIT1()  asm volatile("cp.async.wait_group 1;" ::: "memory")
#define CP_WAIT0()  asm volatile("cp.async.wait_group 0;" ::: "memory")

__device__ __forceinline__ void mma_bf16(float* d, const uint32_t* a, const uint32_t* b) {
    asm volatile(
        "mma.sync.aligned.m16n8k16.row.col.f32.bf16.bf16.f32 "
        "{%0,%1,%2,%3}, {%4,%5,%6,%7}, {%8,%9}, {%0,%1,%2,%3};"
        : "+f"(d[0]), "+f"(d[1]), "+f"(d[2]), "+f"(d[3])
        : "r"(a[0]), "r"(a[1]), "r"(a[2]), "r"(a[3]), "r"(b[0]), "r"(b[1]));
}
__device__ __forceinline__ void ldm_x4(uint32_t* r, uint32_t a) {
    asm volatile("ldmatrix.sync.aligned.m8n8.x4.shared.b16 {%0,%1,%2,%3}, [%4];"
        : "=r"(r[0]), "=r"(r[1]), "=r"(r[2]), "=r"(r[3]) : "r"(a));
}
__device__ __forceinline__ uint32_t pack2(float a, float b) {
    __nv_bfloat162 t = __floats2bfloat162_rn(a, b);
    return *(uint32_t*)&t;
}
__device__ __forceinline__ uint32_t pack2lo(float a, float b) {
    bf16 ha = __float2bfloat16(a), hb = __float2bfloat16(b);
    return pack2(a - __bfloat162float(ha), b - __bfloat162float(hb));
}
__device__ __forceinline__ int expert_of(const int* ex, int chunk, int estride) {
    return ex[chunk * estride];
}

// ------------------------------------------------------------------ split
__global__ void __launch_bounds__(256) split_kernel(
    const float* __restrict__ src, bf16* __restrict__ hi,
    bf16* __restrict__ lo, int n4)
{
    int i = blockIdx.x * blockDim.x + threadIdx.x;
    if (i >= n4) return;
    float4 v = *(const float4*)(src + (size_t)i * 4);
    *(uint32_t*)(hi + (size_t)i * 4)     = pack2(v.x, v.y);
    *(uint32_t*)(hi + (size_t)i * 4 + 2) = pack2(v.z, v.w);
    *(uint32_t*)(lo + (size_t)i * 4)     = pack2lo(v.x, v.y);
    *(uint32_t*)(lo + (size_t)i * 4 + 2) = pack2lo(v.z, v.w);
}

// ------------------------------------------- shared tiling constants
#define KCH      32
#define RPADB    80                  // smem row stride bytes (32 bf16 + pad)
#define ARRB     (128*RPADB)
#define STAGEB   (4*ARRB)
#define NCH_MAIN (DIM/KCH)           // 24
#define NCH_TOT  (NCH_MAIN + 2)
#define MMG_SMEM (2*STAGEB)          // 81920
#define VSTR     132                 // V transpose stage stride (floats)

extern __shared__ char dynsmem[];

// =========================================================================
// 128x128 bf16x3 mainloop (A @ B^T + H @ Be^T) for qkv_gemm
// =========================================================================
struct GemmCtx {
    const bf16 *Ah, *Al, *Wh, *Wl, *Hh, *Hl, *beh, *bel;
    int m0, n0;
};

__device__ __forceinline__ void gemm_mainloop_128(
    const GemmCtx& cx, int tid, float acc[2][8][4])
{
    const int lid = tid & 31;
    const int wid = tid >> 5;
    const int wm  = wid & 3;
    const int wn  = wid >> 2;
    const uint32_t smem_u = s2u(dynsmem);

    const int aRow  = lid & 15;
    const int aHalf = lid >> 4;
    const int bN    = ((lid >> 4) & 1) * 8 + (lid & 7);
    const int bHalf = (lid >> 3) & 1;

    auto issue_load = [&](int c, int s) {
        const bf16 *sa_h, *sa_l, *sb_h, *sb_l;
        int k0, rs;
        if (c < NCH_MAIN) { sa_h = cx.Ah; sa_l = cx.Al; sb_h = cx.Wh;  sb_l = cx.Wl;
                            k0 = c * KCH; rs = DIM; }
        else              { sa_h = cx.Hh; sa_l = cx.Hl; sb_h = cx.beh; sb_l = cx.bel;
                            k0 = (c - NCH_MAIN) * KCH; rs = RR; }
        uint32_t sb = smem_u + s * STAGEB;
        #pragma unroll
        for (int i = 0; i < 2; i++) {
            int idx = tid + i * 256;
            int r   = idx >> 2;
            int cc  = idx & 3;
            uint32_t doff = (uint32_t)(r * RPADB + cc * 16);
            size_t  aoff  = (size_t)(cx.m0 + r) * rs + k0 + cc * 8;
            size_t  boff  = (size_t)(cx.n0 + r) * rs + k0 + cc * 8;
            cpa16(sb + 0 * ARRB + doff, sa_h + aoff);
            cpa16(sb + 1 * ARRB + doff, sa_l + aoff);
            cpa16(sb + 2 * ARRB + doff, sb_h + boff);
            cpa16(sb + 3 * ARRB + doff, sb_l + boff);
        }
    };

    issue_load(0, 0);
    CP_COMMIT();

    for (int c = 0; c < NCH_TOT; c++) {
        const int s = c & 1;
        if (c + 1 < NCH_TOT) { issue_load(c + 1, s ^ 1); CP_COMMIT(); CP_WAIT1(); }
        else                 { CP_WAIT0(); }
        __syncthreads();

        const uint32_t sb = smem_u + s * STAGEB;

        #pragma unroll
        for (int k16 = 0; k16 < KCH / 16; k16++) {
            uint32_t ah[2][4], al[2][4];
            #pragma unroll
            for (int mt = 0; mt < 2; mt++) {
                uint32_t ad = sb + (uint32_t)((wm * 32 + mt * 16 + aRow) * RPADB + k16 * 32 + aHalf * 16);
                ldm_x4(ah[mt], ad);
                ldm_x4(al[mt], ad + ARRB);
            }
            #pragma unroll
            for (int j = 0; j < 4; j++) {
                uint32_t bd = sb + 2 * ARRB +
                    (uint32_t)((wn * 64 + j * 16 + bN) * RPADB + k16 * 32 + bHalf * 16);
                uint32_t t0[4], t1[4];
                ldm_x4(t0, bd);
                ldm_x4(t1, bd + ARRB);
                uint32_t bh0[2] = { t0[0], t0[1] }, bh1[2] = { t0[2], t0[3] };
                uint32_t bl0[2] = { t1[0], t1[1] }, bl1[2] = { t1[2], t1[3] };
                #pragma unroll
                for (int mt = 0; mt < 2; mt++) {
                    mma_bf16(acc[mt][2 * j],     ah[mt], bh0);
                    mma_bf16(acc[mt][2 * j],     ah[mt], bl0);
                    mma_bf16(acc[mt][2 * j],     al[mt], bh0);
                    mma_bf16(acc[mt][2 * j + 1], ah[mt], bh1);
                    mma_bf16(acc[mt][2 * j + 1], ah[mt], bl1);
                    mma_bf16(acc[mt][2 * j + 1], al[mt], bh1);
                }
            }
        }
        __syncthreads();
    }
}

// ---------------------- QKV GEMM with fused attention-operand epilogue
__global__ void __launch_bounds__(256, 2) qkv_gemm(
    const bf16* __restrict__ Ah, const bf16* __restrict__ Al,
    const bf16* __restrict__ Wh, const bf16* __restrict__ Wl,
    const bf16* __restrict__ Hh, const bf16* __restrict__ Hl,
    const bf16* __restrict__ Blh, const bf16* __restrict__ Bll,
    bf16* __restrict__ Qh, bf16* __restrict__ Ql,
    bf16* __restrict__ Kh, bf16* __restrict__ Kl,
    bf16* __restrict__ Vth, bf16* __restrict__ Vtl,
    const int* __restrict__ experts, int estride)
{
    const int tid = threadIdx.x;
    const int lid = tid & 31;
    const int wid = tid >> 5;
    const int wm  = wid & 3;
    const int wn  = wid >> 2;
    const int g   = lid >> 2;
    const int q   = lid & 3;
    const int m0  = blockIdx.y * 128;
    const int n0  = blockIdx.x * 128;
    const int e   = expert_of(experts, (m0 % NSEQ) / CHUNK, estride);

    GemmCtx cx { Ah, Al, Wh, Wl, Hh, Hl,
                 Blh + (size_t)e * QKV_DIM * RR, Bll + (size_t)e * QKV_DIM * RR, m0, n0 };
    float acc[2][8][4] = {};
    gemm_mainloop_128(cx, tid, acc);

    const int seg = n0 / DIM;          // 0 Q, 1 K, 2 V
    const int nc0 = n0 % DIM;

    if (seg < 2) {
        const float sc = (seg == 0) ? (ATT_SCALE * LOG2E) : 1.0f;
        bf16* Dh = (seg == 0) ? Qh : Kh;
        bf16* Dl = (seg == 0) ? Ql : Kl;
        #pragma unroll
        for (int mt = 0; mt < 2; mt++) {
            #pragma unroll
            for (int half = 0; half < 2; half++) {
                int row = m0 + wm * 32 + mt * 16 + g + half * 8;
                int b = row >> 12, n = row & (NSEQ - 1);
                #pragma unroll
                for (int nt = 0; nt < 8; nt++) {
                    int c  = wn * 64 + nt * 8 + q * 2;
                    int nc = nc0 + c;
                    int hh = nc >> 6, d = nc & 63;
                    size_t dst = ((size_t)(b * HEADS + hh) * NSEQ + n) * HD + d;
                    float v0 = acc[mt][nt][half * 2 + 0] * sc;
                    float v1 = acc[mt][nt][half * 2 + 1] * sc;
                    *(uint32_t*)(Dh + dst) = pack2(v0, v1);
                    *(uint32_t*)(Dl + dst) = pack2lo(v0, v1);
                }
            }
        }
    } else {
        float* sm = (float*)dynsmem;
        #pragma unroll
        for (int mt = 0; mt < 2; mt++)
            #pragma unroll
            for (int half = 0; half < 2; half++) {
                int rl = wm * 32 + mt * 16 + g + half * 8;
                #pragma unroll
                for (int nt = 0; nt < 8; nt++) {
                    int c = wn * 64 + nt * 8 + q * 2;
                    sm[rl * VSTR + c]     = acc[mt][nt][half * 2 + 0];
                    sm[rl * VSTR + c + 1] = acc[mt][nt][half * 2 + 1];
                }
            }
        __syncthreads();

        const int bq = m0 >> 12;
        const int nbase = m0 & (NSEQ - 1);
        #pragma unroll
        for (int it = 0; it < 8; it++) {
            int idx = tid + it * 256;
            int c   = idx >> 4;
            int tg  = idx & 15;
            int nc  = nc0 + c;
            int hh  = nc >> 6, d = nc & 63;
            size_t dst = ((size_t)(bq * HEADS + hh) * HD + d) * NSEQ + nbase + tg * 8;
            float v[8];
            #pragma unroll
            for (int i = 0; i < 8; i++) v[i] = sm[(tg * 8 + i) * VSTR + c];
            uint4 whi, wlo;
            whi.x = pack2(v[0], v[1]); whi.y = pack2(v[2], v[3]);
            whi.z = pack2(v[4], v[5]); whi.w = pack2(v[6], v[7]);
            wlo.x = pack2lo(v[0], v[1]); wlo.y = pack2lo(v[2], v[3]);
            wlo.z = pack2lo(v[4], v[5]); wlo.w = pack2lo(v[6], v[7]);
            *(uint4*)(Vth + dst) = whi;
            *(uint4*)(Vtl + dst) = wlo;
        }
    }
}

// ------------------------------------------- HMMA LoRA-A, M=64 tile
// H = split(LSCALE * A @ Ae^T). Grid = TOKENS/64 = 128 blocks.
// 8 warps: wm (4) x 16 rows, wn (2) x 32 cols.
#define L2ARR (64*RPADB)             // 5120 per operand array
#define L2STG (4*L2ARR)              // 20480
#define L2_SMEM (2*L2STG)            // 40960
#define LNCH  (DIM/KCH)              // 24

__global__ void __launch_bounds__(256, 2) lora_mma(
    const bf16* __restrict__ Ah, const bf16* __restrict__ Al,
    const bf16* __restrict__ Aeh, const bf16* __restrict__ Ael,
    bf16* __restrict__ Ch, bf16* __restrict__ Cl,
    const int* __restrict__ experts, int estride)
{
    const int tid = threadIdx.x;
    const int lid = tid & 31;
    const int wid = tid >> 5;
    const int wm  = wid & 3;
    const int wn  = wid >> 2;
    const int g   = lid >> 2;
    const int q   = lid & 3;
    const int m0  = blockIdx.x * 64;
    const int e   = expert_of(experts, (m0 % NSEQ) / CHUNK, estride);

    const bf16* Beh = Aeh + (size_t)e * RR * DIM;
    const bf16* Bel = Ael + (size_t)e * RR * DIM;

    const uint32_t smem_u = s2u(dynsmem);
    const int aRow  = lid & 15;
    const int aHalf = lid >> 4;
    const int bN    = ((lid >> 4) & 1) * 8 + (lid & 7);
    const int bHalf = (lid >> 3) & 1;

    float acc[4][4] = {};

    auto issue_load = [&](int c, int s) {
        int k0 = c * KCH;
        uint32_t sb = smem_u + s * L2STG;
        int r = tid >> 2, cc = tid & 3;          // 64 rows x 4 chunks = 256
        uint32_t doff = (uint32_t)(r * RPADB + cc * 16);
        size_t aoff = (size_t)(m0 + r) * DIM + k0 + cc * 8;
        size_t boff = (size_t)r * DIM + k0 + cc * 8;
        cpa16(sb + 0 * L2ARR + doff, Ah  + aoff);
        cpa16(sb + 1 * L2ARR + doff, Al  + aoff);
        cpa16(sb + 2 * L2ARR + doff, Beh + boff);
        cpa16(sb + 3 * L2ARR + doff, Bel + boff);
    };

    issue_load(0, 0);
    CP_COMMIT();

    for (int c = 0; c < LNCH; c++) {
        const int s = c & 1;
        if (c + 1 < LNCH) { issue_load(c + 1, s ^ 1); CP_COMMIT(); CP_WAIT1(); }
        else              { CP_WAIT0(); }
        __syncthreads();

        const uint32_t sb = smem_u + s * L2STG;
        #pragma unroll
        for (int k16 = 0; k16 < KCH / 16; k16++) {
            uint32_t ah[4], al[4];
            {
                uint32_t ad = sb + (uint32_t)((wm * 16 + aRow) * RPADB + k16 * 32 + aHalf * 16);
                ldm_x4(ah, ad);
                ldm_x4(al, ad + L2ARR);
            }
            #pragma unroll
            for (int j = 0; j < 2; j++) {
                uint32_t bd = sb + 2 * L2ARR +
                    (uint32_t)((wn * 32 + j * 16 + bN) * RPADB + k16 * 32 + bHalf * 16);
                uint32_t t0[4], t1[4];
                ldm_x4(t0, bd);
                ldm_x4(t1, bd + L2ARR);
                uint32_t bh0[2] = { t0[0], t0[1] }, bh1[2] = { t0[2], t0[3] };
                uint32_t bl0[2] = { t1[0], t1[1] }, bl1[2] = { t1[2], t1[3] };
                mma_bf16(acc[2 * j],     ah, bh0);
                mma_bf16(acc[2 * j],     ah, bl0);
                mma_bf16(acc[2 * j],     al, bh0);
                mma_bf16(acc[2 * j + 1], ah, bh1);
                mma_bf16(acc[2 * j + 1], ah, bl1);
                mma_bf16(acc[2 * j + 1], al, bh1);
            }
        }
        __syncthreads();
    }

    const int row0 = m0 + wm * 16 + g;
    #pragma unroll
    for (int nt = 0; nt < 4; nt++) {
        int col = wn * 32 + nt * 8 + q * 2;
        #pragma unroll
        for (int half = 0; half < 2; half++) {
            int row = row0 + half * 8;
            float v0 = acc[nt][half * 2 + 0] * LSCALE;
            float v1 = acc[nt][half * 2 + 1] * LSCALE;
            *(uint32_t*)(Ch + (size_t)row * RR + col) = pack2(v0, v1);
            *(uint32_t*)(Cl + (size_t)row * RR + col) = pack2lo(v0, v1);
        }
    }
}

// ------------------------------------------- proj GEMM, 128x64 tile
// out = o @ Wproj^T + H2 @ Bproj[e]^T. Grid = (DIM/64=12, TOKENS/128=64).
// 8 warps x 16 rows, each warp full 64 cols (8 n-tiles of m16n8).
#define PARRA (128*RPADB)            // 10240
#define PARRB (64*RPADB)             // 5120
#define PSTG  (2*PARRA + 2*PARRB)    // 30720
#define P_SMEM (2*PSTG)              // 61440
#define PNCH  (NCH_MAIN + 2)         // 26

__global__ void __launch_bounds__(256, 2) proj_gemm(
    const bf16* __restrict__ Ah, const bf16* __restrict__ Al,
    const bf16* __restrict__ Wh, const bf16* __restrict__ Wl,
    const bf16* __restrict__ Hh, const bf16* __restrict__ Hl,
    const bf16* __restrict__ Blh, const bf16* __restrict__ Bll,
    float* __restrict__ C, const int* __restrict__ experts, int estride)
{
    const int tid = threadIdx.x;
    const int lid = tid & 31;
    const int wid = tid >> 5;
    const int g   = lid >> 2;
    const int q   = lid & 3;
    const int m0  = blockIdx.y * 128;
    const int n0  = blockIdx.x * 64;
    const int e   = expert_of(experts, (m0 % NSEQ) / CHUNK, estride);

    const bf16* beh = Blh + (size_t)e * DIM * RR;
    const bf16* bel = Bll + (size_t)e * DIM * RR;

    const uint32_t smem_u = s2u(dynsmem);
    const int aRow  = lid & 15;
    const int aHalf = lid >> 4;
    const int bN    = ((lid >> 4) & 1) * 8 + (lid & 7);
    const int bHalf = (lid >> 3) & 1;

    float acc[8][4] = {};

    auto issue_load = [&](int c, int s) {
        const bf16 *sa_h, *sa_l, *sb_h, *sb_l;
        int k0, rs;
        if (c < NCH_MAIN) { sa_h = Ah; sa_l = Al; sb_h = Wh;  sb_l = Wl;
                            k0 = c * KCH; rs = DIM; }
        else              { sa_h = Hh; sa_l = Hl; sb_h = beh; sb_l = bel;
                            k0 = (c - NCH_MAIN) * KCH; rs = RR; }
        uint32_t sb = smem_u + s * PSTG;
        #pragma unroll
        for (int i = 0; i < 2; i++) {            // A: 128 rows x 4 chunks
            int idx = tid + i * 256;
            int r = idx >> 2, cc = idx & 3;
            uint32_t doff = (uint32_t)(r * RPADB + cc * 16);
            size_t aoff = (size_t)(m0 + r) * rs + k0 + cc * 8;
            cpa16(sb + doff,         sa_h + aoff);
            cpa16(sb + PARRA + doff, sa_l + aoff);
        }
        {                                        // B: 64 rows x 4 chunks
            int r = tid >> 2, cc = tid & 3;
            if (r < 64) {
                uint32_t doff = (uint32_t)(r * RPADB + cc * 16);
                size_t boff = (size_t)(n0 + r) * rs + k0 + cc * 8;
                cpa16(sb + 2 * PARRA + doff,         sb_h + boff);
                cpa16(sb + 2 * PARRA + PARRB + doff, sb_l + boff);
            }
        }
    };

    issue_load(0, 0);
    CP_COMMIT();

    for (int c = 0; c < PNCH; c++) {
        const int s = c & 1;
        if (c + 1 < PNCH) { issue_load(c + 1, s ^ 1); CP_COMMIT(); CP_WAIT1(); }
        else              { CP_WAIT0(); }
        __syncthreads();

        const uint32_t sb = smem_u + s * PSTG;
        #pragma unroll
        for (int k16 = 0; k16 < KCH / 16; k16++) {
            uint32_t ah[4], al[4];
            {
                uint32_t ad = sb + (uint32_t)((wid * 16 + aRow) * RPADB + k16 * 32 + aHalf * 16);
                ldm_x4(ah, ad);
                ldm_x4(al, ad + PARRA);
            }
            #pragma unroll
            for (int j = 0; j < 4; j++) {
                uint32_t bd = sb + 2 * PARRA +
                    (uint32_t)((j * 16 + bN) * RPADB + k16 * 32 + bHalf * 16);
                uint32_t t0[4], t1[4];
                ldm_x4(t0, bd);
                ldm_x4(t1, bd + PARRB);
                uint32_t bh0[2] = { t0[0], t0[1] }, bh1[2] = { t0[2], t0[3] };
                uint32_t bl0[2] = { t1[0], t1[1] }, bl1[2] = { t1[2], t1[3] };
                mma_bf16(acc[2 * j],     ah, bh0);
                mma_bf16(acc[2 * j],     ah, bl0);
                mma_bf16(acc[2 * j],     al, bh0);
                mma_bf16(acc[2 * j + 1], ah, bh1);
                mma_bf16(acc[2 * j + 1], ah, bl1);
                mma_bf16(acc[2 * j + 1], al, bh1);
            }
        }
        __syncthreads();
    }

    const int row0 = m0 + wid * 16 + g;
    #pragma unroll
    for (int nt = 0; nt < 8; nt++) {
        int col = n0 + nt * 8 + q * 2;
        *(float2*)(C + (size_t)row0 * DIM + col) =
            make_float2(acc[nt][0], acc[nt][1]);
        *(float2*)(C + (size_t)(row0 + 8) * DIM + col) =
            make_float2(acc[nt][2], acc[nt][3]);
    }
}

// ------------------------------------------ tensor-core flash attention
#define KSTR      72                  // row stride in bf16 elems (144B)
#define ATT_TILE  (64*KSTR*2)         // 9216 B per operand array
#define ATT_STAGE (4*ATT_TILE)        // kh | kl | vh | vl
#define ATT_SMEM  (2*ATT_STAGE)       // 73728

__global__ void __launch_bounds__(256, 1) attn_mma(
    const bf16* __restrict__ Qh, const bf16* __restrict__ Ql,
    const bf16* __restrict__ Kh, const bf16* __restrict__ Kl,
    const bf16* __restrict__ Vth, const bf16* __restrict__ Vtl,
    bf16* __restrict__ Oh, bf16* __restrict__ Ol)
{
    const int qt    = blockIdx.x;
    const int bh    = blockIdx.y;
    const int chunk = (NCHUNKS - 1) - blockIdx.z;   // heavy first
    const int b     = bh / HEADS, h = bh % HEADS;
    const int tid   = threadIdx.x;
    const int w     = tid >> 5, lid = tid & 31;
    const int g     = lid >> 2, q = lid & 3;
    const int klend = (chunk + 1) * CHUNK;

    const bf16* Qbh  = Qh  + (size_t)bh * NSEQ * HD;
    const bf16* Qlbh = Ql  + (size_t)bh * NSEQ * HD;
    const bf16* Kbh  = Kh  + (size_t)bh * NSEQ * HD;
    const bf16* Klbh = Kl  + (size_t)bh * NSEQ * HD;
    const bf16* Vbh  = Vth + (size_t)bh * HD * NSEQ;
    const bf16* Vlbh = Vtl + (size_t)bh * HD * NSEQ;

    const int r0 = chunk * CHUNK + qt * 128 + w * 16 + g;

    uint32_t qhf[4][4], qlf[4][4];
    #pragma unroll
    for (int kk = 0; kk < 4; kk++) {
        size_t base0 = (size_t)r0 * HD + kk * 16 + 2 * q;
        size_t base1 = (size_t)(r0 + 8) * HD + kk * 16 + 2 * q;
        qhf[kk][0] = *(const uint32_t*)(Qbh + base0);
        qhf[kk][1] = *(const uint32_t*)(Qbh + base1);
        qhf[kk][2] = *(const uint32_t*)(Qbh + base0 + 8);
        qhf[kk][3] = *(const uint32_t*)(Qbh + base1 + 8);
        qlf[kk][0] = *(const uint32_t*)(Qlbh + base0);
        qlf[kk][1] = *(const uint32_t*)(Qlbh + base1);
        qlf[kk][2] = *(const uint32_t*)(Qlbh + base0 + 8);
        qlf[kk][3] = *(const uint32_t*)(Qlbh + base1 + 8);
    }

    const uint32_t smem_u = s2u(dynsmem);
    const int bN    = ((lid >> 4) & 1) * 8 + (lid & 7);
    const int bHalf = (lid >> 3) & 1;

    float o[8][4] = {};
    float m0 = -1e30f, m1 = -1e30f, l0 = 0.f, l1 = 0.f;

    auto load_tile = [&](int kt, int s) {
        uint32_t base = smem_u + s * ATT_STAGE;
        #pragma unroll
        for (int i = 0; i < 2; i++) {
            int idx = tid + i * 256;
            int r = idx >> 3, c = idx & 7;
            uint32_t doff = (uint32_t)(r * KSTR + c * 8) * 2;
            cpa16(base + 0 * ATT_TILE + doff, Kbh  + (size_t)(kt + r) * HD + c * 8);
            cpa16(base + 1 * ATT_TILE + doff, Klbh + (size_t)(kt + r) * HD + c * 8);
            cpa16(base + 2 * ATT_TILE + doff, Vbh  + (size_t)r * NSEQ + kt + c * 8);
            cpa16(base + 3 * ATT_TILE + doff, Vlbh + (size_t)r * NSEQ + kt + c * 8);
        }
    };

    const int ntile = klend >> 6;
    load_tile(0, 0);
    CP_COMMIT();

    for (int t = 0; t < ntile; t++) {
        const int s = t & 1;
        if (t + 1 < ntile) { load_tile((t + 1) << 6, s ^ 1); CP_COMMIT(); CP_WAIT1(); }
        else               { CP_WAIT0(); }
        __syncthreads();

        const uint32_t sbK = smem_u + s * ATT_STAGE;
        const uint32_t sbV = sbK + 2 * ATT_TILE;

        float sc[8][4] = {};
        #pragma unroll
        for (int kk = 0; kk < 4; kk++) {
            #pragma unroll
            for (int j = 0; j < 4; j++) {
                uint32_t kd = sbK + (uint32_t)((j * 16 + bN) * KSTR * 2 + kk * 32 + bHalf * 16);
                uint32_t t0[4], t1[4];
                ldm_x4(t0, kd);
                ldm_x4(t1, kd + ATT_TILE);
                uint32_t kb0[2] = { t0[0], t0[1] }, kb1[2] = { t0[2], t0[3] };
                uint32_t kl0[2] = { t1[0], t1[1] }, kl1[2] = { t1[2], t1[3] };
                mma_bf16(sc[2 * j],     qhf[kk], kb0);
                mma_bf16(sc[2 * j],     qhf[kk], kl0);
                mma_bf16(sc[2 * j],     qlf[kk], kb0);
                mma_bf16(sc[2 * j + 1], qhf[kk], kb1);
                mma_bf16(sc[2 * j + 1], qhf[kk], kl1);
                mma_bf16(sc[2 * j + 1], qlf[kk], kb1);
            }
        }

        float mt0 = -1e30f, mt1 = -1e30f;
        #pragma unroll
        for (int nt = 0; nt < 8; nt++) {
            mt0 = fmaxf(mt0, fmaxf(sc[nt][0], sc[nt][1]));
            mt1 = fmaxf(mt1, fmaxf(sc[nt][2], sc[nt][3]));
        }
        mt0 = fmaxf(mt0, __shfl_xor_sync(0xffffffffu, mt0, 1));
        mt0 = fmaxf(mt0, __shfl_xor_sync(0xffffffffu, mt0, 2));
        mt1 = fmaxf(mt1, __shfl_xor_sync(0xffffffffu, mt1, 1));
        mt1 = fmaxf(mt1, __shfl_xor_sync(0xffffffffu, mt1, 2));

        float mn0 = fmaxf(m0, mt0), mn1 = fmaxf(m1, mt1);
        float c0 = ex2f(m0 - mn0), c1 = ex2f(m1 - mn1);
        m0 = mn0; m1 = mn1;
        l0 *= c0; l1 *= c1;

        uint32_t pha[4][4], pla[4][4];
        #pragma unroll
        for (int nt = 0; nt < 8; nt++) {
            float p0 = ex2f(sc[nt][0] - m0);
            float p1 = ex2f(sc[nt][1] - m0);
            float p2 = ex2f(sc[nt][2] - m1);
            float p3 = ex2f(sc[nt][3] - m1);
            l0 += p0 + p1;
            l1 += p2 + p3;
            int kk = nt >> 1, hf = nt & 1;
            pha[kk][hf * 2 + 0] = pack2(p0, p1);
            pha[kk][hf * 2 + 1] = pack2(p2, p3);
            pla[kk][hf * 2 + 0] = pack2lo(p0, p1);
            pla[kk][hf * 2 + 1] = pack2lo(p2, p3);
        }

        #pragma unroll
        for (int nt = 0; nt < 8; nt++) {
            o[nt][0] *= c0; o[nt][1] *= c0;
            o[nt][2] *= c1; o[nt][3] *= c1;
        }

        #pragma unroll
        for (int kk = 0; kk < 4; kk++) {
            #pragma unroll
            for (int j = 0; j < 4; j++) {
                uint32_t vd = sbV + (uint32_t)((j * 16 + bN) * KSTR * 2 + kk * 32 + bHalf * 16);
                uint32_t t0[4], t1[4];
                ldm_x4(t0, vd);
                ldm_x4(t1, vd + ATT_TILE);
                uint32_t vb0[2] = { t0[0], t0[1] }, vb1[2] = { t0[2], t0[3] };
                uint32_t vl0[2] = { t1[0], t1[1] }, vl1[2] = { t1[2], t1[3] };
                mma_bf16(o[2 * j],     pha[kk], vb0);
                mma_bf16(o[2 * j],     pha[kk], vl0);
                mma_bf16(o[2 * j],     pla[kk], vb0);
                mma_bf16(o[2 * j + 1], pha[kk], vb1);
                mma_bf16(o[2 * j + 1], pha[kk], vl1);
                mma_bf16(o[2 * j + 1], pla[kk], vb1);
            }
        }
        __syncthreads();
    }

    l0 += __shfl_xor_sync(0xffffffffu, l0, 1);
    l0 += __shfl_xor_sync(0xffffffffu, l0, 2);
    l1 += __shfl_xor_sync(0xffffffffu, l1, 1);
    l1 += __shfl_xor_sync(0xffffffffu, l1, 2);
    const float inv0 = 1.0f / l0, inv1 = 1.0f / l1;

    size_t off0 = ((size_t)(b * NSEQ + r0)) * DIM + h * HD;
    size_t off1 = ((size_t)(b * NSEQ + r0 + 8)) * DIM + h * HD;
    #pragma unroll
    for (int nt = 0; nt < 8; nt++) {
        int col = nt * 8 + 2 * q;
        float a0 = o[nt][0] * inv0, a1 = o[nt][1] * inv0;
        float b0 = o[nt][2] * inv1, b1 = o[nt][3] * inv1;
        *(uint32_t*)(Oh + off0 + col) = pack2(a0, a1);
        *(uint32_t*)(Ol + off0 + col) = pack2lo(a0, a1);
        *(uint32_t*)(Oh + off1 + col) = pack2(b0, b1);
        *(uint32_t*)(Ol + off1 + col) = pack2lo(b0, b1);
    }
}

// ------------------------------------------------------------------- launch
static inline void run_split(const float* src, bf16* hi, bf16* lo, size_t n) {
    int n4 = (int)(n / 4);
    split_kernel<<<(n4 + 255) / 256, 256>>>(src, hi, lo, n4);
}

extern "C" void kernel_launch(void* const* d_in, const int* in_sizes, int n_in,
                              void* d_out, int out_size)
{
    const float* x       = (const float*)d_in[0];
    const float* Wqkv    = (const float*)d_in[1];
    const float* Aqkv    = (const float*)d_in[2];
    const float* Bqkv    = (const float*)d_in[3];
    const float* Wproj   = (const float*)d_in[4];
    const float* Aproj   = (const float*)d_in[5];
    const float* Bproj   = (const float*)d_in[6];
    const int*   experts = (const int*)d_in[7];
    float*       out     = (float*)d_out;

    int estride = (in_sizes[7] >= 2 * NCHUNKS) ? 2 : 1;

    bf16 *xh, *xl, *oh, *ol, *wqh, *wql, *wph, *wpl;
    bf16 *bqh, *bql, *bph, *bpl, *aqh, *aql, *aph, *apl, *hh, *hl;
    bf16 *qah, *qal, *kah, *kal, *vth, *vtl;
    cudaGetSymbolAddress((void**)&xh,  g_xh);  cudaGetSymbolAddress((void**)&xl,  g_xl);
    cudaGetSymbolAddress((void**)&oh,  g_oh);  cudaGetSymbolAddress((void**)&ol,  g_ol);
    cudaGetSymbolAddress((void**)&wqh, g_wqh); cudaGetSymbolAddress((void**)&wql, g_wql);
    cudaGetSymbolAddress((void**)&wph, g_wph); cudaGetSymbolAddress((void**)&wpl, g_wpl);
    cudaGetSymbolAddress((void**)&bqh, g_bqh); cudaGetSymbolAddress((void**)&bql, g_bql);
    cudaGetSymbolAddress((void**)&bph, g_bph); cudaGetSymbolAddress((void**)&bpl, g_bpl);
    cudaGetSymbolAddress((void**)&aqh, g_aqh); cudaGetSymbolAddress((void**)&aql, g_aql);
    cudaGetSymbolAddress((void**)&aph, g_aph); cudaGetSymbolAddress((void**)&apl, g_apl);
    cudaGetSymbolAddress((void**)&hh,  g_hh);  cudaGetSymbolAddress((void**)&hl,  g_hl);
    cudaGetSymbolAddress((void**)&qah, g_qah); cudaGetSymbolAddress((void**)&qal, g_qal);
    cudaGetSymbolAddress((void**)&kah, g_kah); cudaGetSymbolAddress((void**)&kal, g_kal);
    cudaGetSymbolAddress((void**)&vth, g_vth); cudaGetSymbolAddress((void**)&vtl, g_vtl);

    cudaFuncSetAttribute(qkv_gemm, cudaFuncAttributeMaxDynamicSharedMemorySize, MMG_SMEM);
    cudaFuncSetAttribute(proj_gemm, cudaFuncAttributeMaxDynamicSharedMemorySize, P_SMEM);
    cudaFuncSetAttribute(lora_mma, cudaFuncAttributeMaxDynamicSharedMemorySize, L2_SMEM);
    cudaFuncSetAttribute(attn_mma, cudaFuncAttributeMaxDynamicSharedMemorySize, ATT_SMEM);

    // 0) split fp32 operands into bf16 hi/lo
    run_split(x,     xh,  xl,  (size_t)TOKENS * DIM);
    run_split(Wqkv,  wqh, wql, (size_t)QKV_DIM * DIM);
    run_split(Bqkv,  bqh, bql, (size_t)NEXP * QKV_DIM * RR);
    run_split(Wproj, wph, wpl, (size_t)DIM * DIM);
    run_split(Bproj, bph, bpl, (size_t)NEXP * DIM * RR);
    run_split(Aqkv,  aqh, aql, (size_t)NEXP * RR * DIM);
    run_split(Aproj, aph, apl, (size_t)NEXP * RR * DIM);

    // 1) H = split(LSCALE * x @ Aqkv[e]^T)
    lora_mma<<<TOKENS / 64, 256, L2_SMEM>>>(xh, xl, aqh, aql, hh, hl, experts, estride);

    // 2) QKV GEMM with fused attention-operand epilogue
    {
        dim3 grid(QKV_DIM / 128, TOKENS / 128);
        qkv_gemm<<<grid, 256, MMG_SMEM>>>(xh, xl, wqh, wql, hh, hl, bqh, bql,
                                          qah, qal, kah, kal, vth, vtl,
                                          experts, estride);
    }

    // 3) tensor-core chunked block-causal attention (writes split o)
    {
        dim3 grid(CHUNK / 128, BB * HEADS, NCHUNKS);
        attn_mma<<<grid, 256, ATT_SMEM>>>(qah, qal, kah, kal, vth, vtl, oh, ol);
    }

    // 4) H2 = split(LSCALE * o @ Aproj[e]^T)
    lora_mma<<<TOKENS / 64, 256, L2_SMEM>>>(oh, ol, aph, apl, hh, hl, experts, estride);

    // 5) out = o @ Wproj^T + H2 @ Bproj[e]^T (128x64 tiles)
    {
        dim3 grid(DIM / 64, TOKENS / 128);
        proj_gemm<<<grid, 256, P_SMEM>>>(oh, ol, wph, wpl, hh, hl, bph, bpl,
                                         out, experts, estride);
    }
}

// round 12
// speedup vs baseline: 1.0274x; 1.0274x over previous
#include <cuda_runtime.h>
#include <cuda_bf16.h>
#include <cstdint>
#include <cstddef>

#define DIM     768
#define HEADS   12
#define HD      64
#define RR      64
#define BB      2
#define NSEQ    4096
#define CHUNK   1024
#define NCHUNKS 4
#define TOKENS  (BB*NSEQ)     // 8192
#define QKV_DIM (3*DIM)       // 2304
#define NEXP    8
#define LSCALE  2.0f          // 128 / 64
#define ATT_SCALE 0.125f      // 64^-0.5
#define LOG2E   1.4426950408889634f

typedef __nv_bfloat16 bf16;

// ------------------------------------------------------------------ scratch
__device__ __align__(16) bf16 g_xh [(size_t)TOKENS * DIM],   g_xl [(size_t)TOKENS * DIM];
__device__ __align__(16) bf16 g_oh [(size_t)TOKENS * DIM],   g_ol [(size_t)TOKENS * DIM];
__device__ __align__(16) bf16 g_wqh[(size_t)QKV_DIM * DIM],  g_wql[(size_t)QKV_DIM * DIM];
__device__ __align__(16) bf16 g_wph[(size_t)DIM * DIM],      g_wpl[(size_t)DIM * DIM];
__device__ __align__(16) bf16 g_bqh[(size_t)NEXP * QKV_DIM * RR], g_bql[(size_t)NEXP * QKV_DIM * RR];
__device__ __align__(16) bf16 g_bph[(size_t)NEXP * DIM * RR],     g_bpl[(size_t)NEXP * DIM * RR];
__device__ __align__(16) bf16 g_aqh[(size_t)NEXP * RR * DIM],     g_aql[(size_t)NEXP * RR * DIM];
__device__ __align__(16) bf16 g_aph[(size_t)NEXP * RR * DIM],     g_apl[(size_t)NEXP * RR * DIM];
__device__ __align__(16) bf16 g_hh [(size_t)TOKENS * RR],    g_hl [(size_t)TOKENS * RR];

__device__ __align__(16) bf16 g_qah[(size_t)BB*HEADS*NSEQ*HD], g_qal[(size_t)BB*HEADS*NSEQ*HD];
__device__ __align__(16) bf16 g_kah[(size_t)BB*HEADS*NSEQ*HD], g_kal[(size_t)BB*HEADS*NSEQ*HD];
__device__ __align__(16) bf16 g_vth[(size_t)BB*HEADS*HD*NSEQ], g_vtl[(size_t)BB*HEADS*HD*NSEQ];

// ------------------------------------------------------------------ helpers
__device__ __forceinline__ float ex2f(float x) {
    float y; asm("ex2.approx.f32 %0, %1;" : "=f"(y) : "f"(x)); return y;
}
__device__ __forceinline__ uint32_t s2u(const void* p) {
    uint32_t a;
    asm("{ .reg .u64 t; cvta.to.shared.u64 t, %1; cvt.u32.u64 %0, t; }" : "=r"(a) : "l"(p));
    return a;
}
__device__ __forceinline__ void cpa16(uint32_t d, const void* s) {
    asm volatile("cp.async.cg.shared.global [%0], [%1], 16;" :: "r"(d), "l"(s));
}
#define CP_COMMIT() asm volatile("cp.async.commit_group;" ::: "memory")
#define CP_WAIT2()  asm volatile("cp.async.wait_group 2;" ::: "memory")
#define CP_WAIT1()  asm volatile("cp.async.wait_group 1;" ::: "memory")
#define CP_WAIT0()  asm volatile("cp.async.wait_group 0;" ::: "memory")

__device__ __forceinline__ void mma_bf16(float* d, const uint32_t* a, const uint32_t* b) {
    asm volatile(
        "mma.sync.aligned.m16n8k16.row.col.f32.bf16.bf16.f32 "
        "{%0,%1,%2,%3}, {%4,%5,%6,%7}, {%8,%9}, {%0,%1,%2,%3};"
        : "+f"(d[0]), "+f"(d[1]), "+f"(d[2]), "+f"(d[3])
        : "r"(a[0]), "r"(a[1]), "r"(a[2]), "r"(a[3]), "r"(b[0]), "r"(b[1]));
}
__device__ __forceinline__ void ldm_x4(uint32_t* r, uint32_t a) {
    asm volatile("ldmatrix.sync.aligned.m8n8.x4.shared.b16 {%0,%1,%2,%3}, [%4];"
        : "=r"(r[0]), "=r"(r[1]), "=r"(r[2]), "=r"(r[3]) : "r"(a));
}
__device__ __forceinline__ uint32_t pack2(float a, float b) {
    __nv_bfloat162 t = __floats2bfloat162_rn(a, b);
    return *(uint32_t*)&t;
}
__device__ __forceinline__ uint32_t pack2lo(float a, float b) {
    bf16 ha = __float2bfloat16(a), hb = __float2bfloat16(b);
    return pack2(a - __bfloat162float(ha), b - __bfloat162float(hb));
}
__device__ __forceinline__ int expert_of(const int* ex, int chunk, int estride) {
    return ex[chunk * estride];
}

// ------------------------------------------------------ fused split (7 ops)
#define N4_X   (TOKENS*DIM/4)          // 1,572,864
#define N4_WQ  (QKV_DIM*DIM/4)         //   442,368
#define N4_BQ  (NEXP*QKV_DIM*RR/4)     //   294,912
#define N4_WP  (DIM*DIM/4)             //   147,456
#define N4_BP  (NEXP*DIM*RR/4)         //    98,304
#define N4_AQ  (NEXP*RR*DIM/4)         //    98,304
#define N4_AP  (NEXP*RR*DIM/4)         //    98,304
#define C4_0   N4_X
#define C4_1   (C4_0 + N4_WQ)
#define C4_2   (C4_1 + N4_BQ)
#define C4_3   (C4_2 + N4_WP)
#define C4_4   (C4_3 + N4_BP)
#define C4_5   (C4_4 + N4_AQ)
#define C4_6   (C4_5 + N4_AP)          // total = 2,752,512

struct SplitArgs {
    const float* src[7];
    bf16* hi[7];
    bf16* lo[7];
};

__global__ void __launch_bounds__(256) split_all(SplitArgs sa)
{
    int i = blockIdx.x * blockDim.x + threadIdx.x;
    if (i >= C4_6) return;
    int seg, base;
    if      (i < C4_0) { seg = 0; base = 0;    }
    else if (i < C4_1) { seg = 1; base = C4_0; }
    else if (i < C4_2) { seg = 2; base = C4_1; }
    else if (i < C4_3) { seg = 3; base = C4_2; }
    else if (i < C4_4) { seg = 4; base = C4_3; }
    else if (i < C4_5) { seg = 5; base = C4_4; }
    else               { seg = 6; base = C4_5; }
    size_t j = (size_t)(i - base) * 4;
    float4 v = *(const float4*)(sa.src[seg] + j);
    *(uint32_t*)(sa.hi[seg] + j)     = pack2(v.x, v.y);
    *(uint32_t*)(sa.hi[seg] + j + 2) = pack2(v.z, v.w);
    *(uint32_t*)(sa.lo[seg] + j)     = pack2lo(v.x, v.y);
    *(uint32_t*)(sa.lo[seg] + j + 2) = pack2lo(v.z, v.w);
}

// ------------------------------------------- shared tiling constants
#define KCH      32
#define RPADB    80                  // smem row stride bytes (32 bf16 + pad)
#define ARRB     (128*RPADB)
#define STAGEB   (4*ARRB)
#define NCH_MAIN (DIM/KCH)           // 24
#define NCH_TOT  (NCH_MAIN + 2)
#define MMG_SMEM (2*STAGEB)          // 81920
#define VSTR     132                 // fp32 staging stride (floats)

extern __shared__ char dynsmem[];

// =========================================================================
// 128x128 bf16x3 mainloop (A @ B^T + H @ Be^T) for qkv_gemm
// =========================================================================
struct GemmCtx {
    const bf16 *Ah, *Al, *Wh, *Wl, *Hh, *Hl, *beh, *bel;
    int m0, n0;
};

__device__ __forceinline__ void gemm_mainloop_128(
    const GemmCtx& cx, int tid, float acc[2][8][4])
{
    const int lid = tid & 31;
    const int wid = tid >> 5;
    const int wm  = wid & 3;
    const int wn  = wid >> 2;
    const uint32_t smem_u = s2u(dynsmem);

    const int aRow  = lid & 15;
    const int aHalf = lid >> 4;
    const int bN    = ((lid >> 4) & 1) * 8 + (lid & 7);
    const int bHalf = (lid >> 3) & 1;

    auto issue_load = [&](int c, int s) {
        const bf16 *sa_h, *sa_l, *sb_h, *sb_l;
        int k0, rs;
        if (c < NCH_MAIN) { sa_h = cx.Ah; sa_l = cx.Al; sb_h = cx.Wh;  sb_l = cx.Wl;
                            k0 = c * KCH; rs = DIM; }
        else              { sa_h = cx.Hh; sa_l = cx.Hl; sb_h = cx.beh; sb_l = cx.bel;
                            k0 = (c - NCH_MAIN) * KCH; rs = RR; }
        uint32_t sb = smem_u + s * STAGEB;
        #pragma unroll
        for (int i = 0; i < 2; i++) {
            int idx = tid + i * 256;
            int r   = idx >> 2;
            int cc  = idx & 3;
            uint32_t doff = (uint32_t)(r * RPADB + cc * 16);
            size_t  aoff  = (size_t)(cx.m0 + r) * rs + k0 + cc * 8;
            size_t  boff  = (size_t)(cx.n0 + r) * rs + k0 + cc * 8;
            cpa16(sb + 0 * ARRB + doff, sa_h + aoff);
            cpa16(sb + 1 * ARRB + doff, sa_l + aoff);
            cpa16(sb + 2 * ARRB + doff, sb_h + boff);
            cpa16(sb + 3 * ARRB + doff, sb_l + boff);
        }
    };

    issue_load(0, 0);
    CP_COMMIT();

    for (int c = 0; c < NCH_TOT; c++) {
        const int s = c & 1;
        if (c + 1 < NCH_TOT) { issue_load(c + 1, s ^ 1); CP_COMMIT(); CP_WAIT1(); }
        else                 { CP_WAIT0(); }
        __syncthreads();

        const uint32_t sb = smem_u + s * STAGEB;

        #pragma unroll
        for (int k16 = 0; k16 < KCH / 16; k16++) {
            uint32_t ah[2][4], al[2][4];
            #pragma unroll
            for (int mt = 0; mt < 2; mt++) {
                uint32_t ad = sb + (uint32_t)((wm * 32 + mt * 16 + aRow) * RPADB + k16 * 32 + aHalf * 16);
                ldm_x4(ah[mt], ad);
                ldm_x4(al[mt], ad + ARRB);
            }
            #pragma unroll
            for (int j = 0; j < 4; j++) {
                uint32_t bd = sb + 2 * ARRB +
                    (uint32_t)((wn * 64 + j * 16 + bN) * RPADB + k16 * 32 + bHalf * 16);
                uint32_t t0[4], t1[4];
                ldm_x4(t0, bd);
                ldm_x4(t1, bd + ARRB);
                uint32_t bh0[2] = { t0[0], t0[1] }, bh1[2] = { t0[2], t0[3] };
                uint32_t bl0[2] = { t1[0], t1[1] }, bl1[2] = { t1[2], t1[3] };
                #pragma unroll
                for (int mt = 0; mt < 2; mt++) {
                    mma_bf16(acc[mt][2 * j],     ah[mt], bh0);
                    mma_bf16(acc[mt][2 * j],     ah[mt], bl0);
                    mma_bf16(acc[mt][2 * j],     al[mt], bh0);
                    mma_bf16(acc[mt][2 * j + 1], ah[mt], bh1);
                    mma_bf16(acc[mt][2 * j + 1], ah[mt], bl1);
                    mma_bf16(acc[mt][2 * j + 1], al[mt], bh1);
                }
            }
        }
        __syncthreads();
    }
}

// ---------------------- QKV GEMM with fused attention-operand epilogue
// All segments stage fp32 results through smem for coalesced split writes.
__global__ void __launch_bounds__(256, 2) qkv_gemm(
    const bf16* __restrict__ Ah, const bf16* __restrict__ Al,
    const bf16* __restrict__ Wh, const bf16* __restrict__ Wl,
    const bf16* __restrict__ Hh, const bf16* __restrict__ Hl,
    const bf16* __restrict__ Blh, const bf16* __restrict__ Bll,
    bf16* __restrict__ Qh, bf16* __restrict__ Ql,
    bf16* __restrict__ Kh, bf16* __restrict__ Kl,
    bf16* __restrict__ Vth, bf16* __restrict__ Vtl,
    const int* __restrict__ experts, int estride)
{
    const int tid = threadIdx.x;
    const int lid = tid & 31;
    const int wid = tid >> 5;
    const int wm  = wid & 3;
    const int wn  = wid >> 2;
    const int g   = lid >> 2;
    const int q   = lid & 3;
    const int m0  = blockIdx.y * 128;
    const int n0  = blockIdx.x * 128;
    const int e   = expert_of(experts, (m0 % NSEQ) / CHUNK, estride);

    GemmCtx cx { Ah, Al, Wh, Wl, Hh, Hl,
                 Blh + (size_t)e * QKV_DIM * RR, Bll + (size_t)e * QKV_DIM * RR, m0, n0 };
    float acc[2][8][4] = {};
    gemm_mainloop_128(cx, tid, acc);

    const int seg = n0 / DIM;          // 0 Q, 1 K, 2 V
    const int nc0 = n0 % DIM;
    const float sc = (seg == 0) ? (ATT_SCALE * LOG2E) : 1.0f;

    // stage scaled fp32 tile into smem (mainloop ended with __syncthreads)
    float* sm = (float*)dynsmem;
    #pragma unroll
    for (int mt = 0; mt < 2; mt++)
        #pragma unroll
        for (int half = 0; half < 2; half++) {
            int rl = wm * 32 + mt * 16 + g + half * 8;
            #pragma unroll
            for (int nt = 0; nt < 8; nt++) {
                int c = wn * 64 + nt * 8 + q * 2;
                sm[rl * VSTR + c]     = acc[mt][nt][half * 2 + 0] * sc;
                sm[rl * VSTR + c + 1] = acc[mt][nt][half * 2 + 1] * sc;
            }
        }
    __syncthreads();

    if (seg < 2) {
        bf16* Dh = (seg == 0) ? Qh : Kh;
        bf16* Dl = (seg == 0) ? Ql : Kl;
        const int bq = m0 >> 12;
        const int nbase = m0 & (NSEQ - 1);
        // each thread: one row (r) x one 8-float chunk (c8) -> uint4 hi + lo
        #pragma unroll
        for (int it = 0; it < 8; it++) {
            int idx = tid + it * 256;        // 0..2047
            int r   = idx >> 4;              // 0..127
            int c8  = idx & 15;              // 0..15 chunks of 8 floats
            int nc  = nc0 + c8 * 8;
            int hh  = nc >> 6, d = nc & 63;
            size_t dst = ((size_t)(bq * HEADS + hh) * NSEQ + nbase + r) * HD + d;
            const float* sp = sm + r * VSTR + c8 * 8;
            uint4 whi, wlo;
            whi.x = pack2(sp[0], sp[1]); whi.y = pack2(sp[2], sp[3]);
            whi.z = pack2(sp[4], sp[5]); whi.w = pack2(sp[6], sp[7]);
            wlo.x = pack2lo(sp[0], sp[1]); wlo.y = pack2lo(sp[2], sp[3]);
            wlo.z = pack2lo(sp[4], sp[5]); wlo.w = pack2lo(sp[6], sp[7]);
            *(uint4*)(Dh + dst) = whi;
            *(uint4*)(Dl + dst) = wlo;
        }
    } else {
        const int bq = m0 >> 12;
        const int nbase = m0 & (NSEQ - 1);
        #pragma unroll
        for (int it = 0; it < 8; it++) {
            int idx = tid + it * 256;
            int c   = idx >> 4;              // col 0..127
            int tg  = idx & 15;              // token group of 8
            int nc  = nc0 + c;
            int hh  = nc >> 6, d = nc & 63;
            size_t dst = ((size_t)(bq * HEADS + hh) * HD + d) * NSEQ + nbase + tg * 8;
            float v[8];
            #pragma unroll
            for (int i = 0; i < 8; i++) v[i] = sm[(tg * 8 + i) * VSTR + c];
            uint4 whi, wlo;
            whi.x = pack2(v[0], v[1]); whi.y = pack2(v[2], v[3]);
            whi.z = pack2(v[4], v[5]); whi.w = pack2(v[6], v[7]);
            wlo.x = pack2lo(v[0], v[1]); wlo.y = pack2lo(v[2], v[3]);
            wlo.z = pack2lo(v[4], v[5]); wlo.w = pack2lo(v[6], v[7]);
            *(uint4*)(Vth + dst) = whi;
            *(uint4*)(Vtl + dst) = wlo;
        }
    }
}

// ------------------------------------------- HMMA LoRA-A, M=64 tile
#define L2ARR (64*RPADB)             // 5120 per operand array
#define L2STG (4*L2ARR)              // 20480
#define L2_SMEM (2*L2STG)            // 40960
#define LNCH  (DIM/KCH)              // 24

__global__ void __launch_bounds__(256, 2) lora_mma(
    const bf16* __restrict__ Ah, const bf16* __restrict__ Al,
    const bf16* __restrict__ Aeh, const bf16* __restrict__ Ael,
    bf16* __restrict__ Ch, bf16* __restrict__ Cl,
    const int* __restrict__ experts, int estride)
{
    const int tid = threadIdx.x;
    const int lid = tid & 31;
    const int wid = tid >> 5;
    const int wm  = wid & 3;
    const int wn  = wid >> 2;
    const int g   = lid >> 2;
    const int q   = lid & 3;
    const int m0  = blockIdx.x * 64;
    const int e   = expert_of(experts, (m0 % NSEQ) / CHUNK, estride);

    const bf16* Beh = Aeh + (size_t)e * RR * DIM;
    const bf16* Bel = Ael + (size_t)e * RR * DIM;

    const uint32_t smem_u = s2u(dynsmem);
    const int aRow  = lid & 15;
    const int aHalf = lid >> 4;
    const int bN    = ((lid >> 4) & 1) * 8 + (lid & 7);
    const int bHalf = (lid >> 3) & 1;

    float acc[4][4] = {};

    auto issue_load = [&](int c, int s) {
        int k0 = c * KCH;
        uint32_t sb = smem_u + s * L2STG;
        int r = tid >> 2, cc = tid & 3;
        uint32_t doff = (uint32_t)(r * RPADB + cc * 16);
        size_t aoff = (size_t)(m0 + r) * DIM + k0 + cc * 8;
        size_t boff = (size_t)r * DIM + k0 + cc * 8;
        cpa16(sb + 0 * L2ARR + doff, Ah  + aoff);
        cpa16(sb + 1 * L2ARR + doff, Al  + aoff);
        cpa16(sb + 2 * L2ARR + doff, Beh + boff);
        cpa16(sb + 3 * L2ARR + doff, Bel + boff);
    };

    issue_load(0, 0);
    CP_COMMIT();

    for (int c = 0; c < LNCH; c++) {
        const int s = c & 1;
        if (c + 1 < LNCH) { issue_load(c + 1, s ^ 1); CP_COMMIT(); CP_WAIT1(); }
        else              { CP_WAIT0(); }
        __syncthreads();

        const uint32_t sb = smem_u + s * L2STG;
        #pragma unroll
        for (int k16 = 0; k16 < KCH / 16; k16++) {
            uint32_t ah[4], al[4];
            {
                uint32_t ad = sb + (uint32_t)((wm * 16 + aRow) * RPADB + k16 * 32 + aHalf * 16);
                ldm_x4(ah, ad);
                ldm_x4(al, ad + L2ARR);
            }
            #pragma unroll
            for (int j = 0; j < 2; j++) {
                uint32_t bd = sb + 2 * L2ARR +
                    (uint32_t)((wn * 32 + j * 16 + bN) * RPADB + k16 * 32 + bHalf * 16);
                uint32_t t0[4], t1[4];
                ldm_x4(t0, bd);
                ldm_x4(t1, bd + L2ARR);
                uint32_t bh0[2] = { t0[0], t0[1] }, bh1[2] = { t0[2], t0[3] };
                uint32_t bl0[2] = { t1[0], t1[1] }, bl1[2] = { t1[2], t1[3] };
                mma_bf16(acc[2 * j],     ah, bh0);
                mma_bf16(acc[2 * j],     ah, bl0);
                mma_bf16(acc[2 * j],     al, bh0);
                mma_bf16(acc[2 * j + 1], ah, bh1);
                mma_bf16(acc[2 * j + 1], ah, bl1);
                mma_bf16(acc[2 * j + 1], al, bh1);
            }
        }
        __syncthreads();
    }

    const int row0 = m0 + wm * 16 + g;
    #pragma unroll
    for (int nt = 0; nt < 4; nt++) {
        int col = wn * 32 + nt * 8 + q * 2;
        #pragma unroll
        for (int half = 0; half < 2; half++) {
            int row = row0 + half * 8;
            float v0 = acc[nt][half * 2 + 0] * LSCALE;
            float v1 = acc[nt][half * 2 + 1] * LSCALE;
            *(uint32_t*)(Ch + (size_t)row * RR + col) = pack2(v0, v1);
            *(uint32_t*)(Cl + (size_t)row * RR + col) = pack2lo(v0, v1);
        }
    }
}

// ------------------------------------------- proj GEMM, 128x64 tile
#define PARRA (128*RPADB)            // 10240
#define PARRB (64*RPADB)             // 5120
#define PSTG  (2*PARRA + 2*PARRB)    // 30720
#define P_SMEM (2*PSTG)              // 61440
#define PNCH  (NCH_MAIN + 2)         // 26

__global__ void __launch_bounds__(256, 2) proj_gemm(
    const bf16* __restrict__ Ah, const bf16* __restrict__ Al,
    const bf16* __restrict__ Wh, const bf16* __restrict__ Wl,
    const bf16* __restrict__ Hh, const bf16* __restrict__ Hl,
    const bf16* __restrict__ Blh, const bf16* __restrict__ Bll,
    float* __restrict__ C, const int* __restrict__ experts, int estride)
{
    const int tid = threadIdx.x;
    const int lid = tid & 31;
    const int wid = tid >> 5;
    const int g   = lid >> 2;
    const int q   = lid & 3;
    const int m0  = blockIdx.y * 128;
    const int n0  = blockIdx.x * 64;
    const int e   = expert_of(experts, (m0 % NSEQ) / CHUNK, estride);

    const bf16* beh = Blh + (size_t)e * DIM * RR;
    const bf16* bel = Bll + (size_t)e * DIM * RR;

    const uint32_t smem_u = s2u(dynsmem);
    const int aRow  = lid & 15;
    const int aHalf = lid >> 4;
    const int bN    = ((lid >> 4) & 1) * 8 + (lid & 7);
    const int bHalf = (lid >> 3) & 1;

    float acc[8][4] = {};

    auto issue_load = [&](int c, int s) {
        const bf16 *sa_h, *sa_l, *sb_h, *sb_l;
        int k0, rs;
        if (c < NCH_MAIN) { sa_h = Ah; sa_l = Al; sb_h = Wh;  sb_l = Wl;
                            k0 = c * KCH; rs = DIM; }
        else              { sa_h = Hh; sa_l = Hl; sb_h = beh; sb_l = bel;
                            k0 = (c - NCH_MAIN) * KCH; rs = RR; }
        uint32_t sb = smem_u + s * PSTG;
        #pragma unroll
        for (int i = 0; i < 2; i++) {
            int idx = tid + i * 256;
            int r = idx >> 2, cc = idx & 3;
            uint32_t doff = (uint32_t)(r * RPADB + cc * 16);
            size_t aoff = (size_t)(m0 + r) * rs + k0 + cc * 8;
            cpa16(sb + doff,         sa_h + aoff);
            cpa16(sb + PARRA + doff, sa_l + aoff);
        }
        {
            int r = tid >> 2, cc = tid & 3;
            if (r < 64) {
                uint32_t doff = (uint32_t)(r * RPADB + cc * 16);
                size_t boff = (size_t)(n0 + r) * rs + k0 + cc * 8;
                cpa16(sb + 2 * PARRA + doff,         sb_h + boff);
                cpa16(sb + 2 * PARRA + PARRB + doff, sb_l + boff);
            }
        }
    };

    issue_load(0, 0);
    CP_COMMIT();

    for (int c = 0; c < PNCH; c++) {
        const int s = c & 1;
        if (c + 1 < PNCH) { issue_load(c + 1, s ^ 1); CP_COMMIT(); CP_WAIT1(); }
        else              { CP_WAIT0(); }
        __syncthreads();

        const uint32_t sb = smem_u + s * PSTG;
        #pragma unroll
        for (int k16 = 0; k16 < KCH / 16; k16++) {
            uint32_t ah[4], al[4];
            {
                uint32_t ad = sb + (uint32_t)((wid * 16 + aRow) * RPADB + k16 * 32 + aHalf * 16);
                ldm_x4(ah, ad);
                ldm_x4(al, ad + PARRA);
            }
            #pragma unroll
            for (int j = 0; j < 4; j++) {
                uint32_t bd = sb + 2 * PARRA +
                    (uint32_t)((j * 16 + bN) * RPADB + k16 * 32 + bHalf * 16);
                uint32_t t0[4], t1[4];
                ldm_x4(t0, bd);
                ldm_x4(t1, bd + PARRB);
                uint32_t bh0[2] = { t0[0], t0[1] }, bh1[2] = { t0[2], t0[3] };
                uint32_t bl0[2] = { t1[0], t1[1] }, bl1[2] = { t1[2], t1[3] };
                mma_bf16(acc[2 * j],     ah, bh0);
                mma_bf16(acc[2 * j],     ah, bl0);
                mma_bf16(acc[2 * j],     al, bh0);
                mma_bf16(acc[2 * j + 1], ah, bh1);
                mma_bf16(acc[2 * j + 1], ah, bl1);
                mma_bf16(acc[2 * j + 1], al, bh1);
            }
        }
        __syncthreads();
    }

    const int row0 = m0 + wid * 16 + g;
    #pragma unroll
    for (int nt = 0; nt < 8; nt++) {
        int col = n0 + nt * 8 + q * 2;
        *(float2*)(C + (size_t)row0 * DIM + col) =
            make_float2(acc[nt][0], acc[nt][1]);
        *(float2*)(C + (size_t)(row0 + 8) * DIM + col) =
            make_float2(acc[nt][2], acc[nt][3]);
    }
}

// ------------------------------------------ tensor-core flash attention
// 128 q-rows, 8 warps, 64-key tiles, 3-stage cp.async ring, 1 barrier/tile.
#define KSTR      72                  // row stride in bf16 elems (144B)
#define ATT_TILE  (64*KSTR*2)         // 9216 B per operand array
#define ATT_STAGE (4*ATT_TILE)        // kh | kl | vh | vl
#define ATT_SMEM  (3*ATT_STAGE)       // 110592

__global__ void __launch_bounds__(256, 1) attn_mma(
    const bf16* __restrict__ Qh, const bf16* __restrict__ Ql,
    const bf16* __restrict__ Kh, const bf16* __restrict__ Kl,
    const bf16* __restrict__ Vth, const bf16* __restrict__ Vtl,
    bf16* __restrict__ Oh, bf16* __restrict__ Ol)
{
    const int qt    = blockIdx.x;
    const int bh    = blockIdx.y;
    const int chunk = (NCHUNKS - 1) - blockIdx.z;   // heavy first
    const int b     = bh / HEADS, h = bh % HEADS;
    const int tid   = threadIdx.x;
    const int w     = tid >> 5, lid = tid & 31;
    const int g     = lid >> 2, q = lid & 3;
    const int klend = (chunk + 1) * CHUNK;

    const bf16* Qbh  = Qh  + (size_t)bh * NSEQ * HD;
    const bf16* Qlbh = Ql  + (size_t)bh * NSEQ * HD;
    const bf16* Kbh  = Kh  + (size_t)bh * NSEQ * HD;
    const bf16* Klbh = Kl  + (size_t)bh * NSEQ * HD;
    const bf16* Vbh  = Vth + (size_t)bh * HD * NSEQ;
    const bf16* Vlbh = Vtl + (size_t)bh * HD * NSEQ;

    const int r0 = chunk * CHUNK + qt * 128 + w * 16 + g;

    uint32_t qhf[4][4], qlf[4][4];
    #pragma unroll
    for (int kk = 0; kk < 4; kk++) {
        size_t base0 = (size_t)r0 * HD + kk * 16 + 2 * q;
        size_t base1 = (size_t)(r0 + 8) * HD + kk * 16 + 2 * q;
        qhf[kk][0] = *(const uint32_t*)(Qbh + base0);
        qhf[kk][1] = *(const uint32_t*)(Qbh + base1);
        qhf[kk][2] = *(const uint32_t*)(Qbh + base0 + 8);
        qhf[kk][3] = *(const uint32_t*)(Qbh + base1 + 8);
        qlf[kk][0] = *(const uint32_t*)(Qlbh + base0);
        qlf[kk][1] = *(const uint32_t*)(Qlbh + base1);
        qlf[kk][2] = *(const uint32_t*)(Qlbh + base0 + 8);
        qlf[kk][3] = *(const uint32_t*)(Qlbh + base1 + 8);
    }

    const uint32_t smem_u = s2u(dynsmem);
    const int bN    = ((lid >> 4) & 1) * 8 + (lid & 7);
    const int bHalf = (lid >> 3) & 1;

    float o[8][4] = {};
    float m0 = -1e30f, m1 = -1e30f, l0 = 0.f, l1 = 0.f;

    auto load_tile = [&](int kt, int s) {
        uint32_t base = smem_u + s * ATT_STAGE;
        #pragma unroll
        for (int i = 0; i < 2; i++) {
            int idx = tid + i * 256;
            int r = idx >> 3, c = idx & 7;
            uint32_t doff = (uint32_t)(r * KSTR + c * 8) * 2;
            cpa16(base + 0 * ATT_TILE + doff, Kbh  + (size_t)(kt + r) * HD + c * 8);
            cpa16(base + 1 * ATT_TILE + doff, Klbh + (size_t)(kt + r) * HD + c * 8);
            cpa16(base + 2 * ATT_TILE + doff, Vbh  + (size_t)r * NSEQ + kt + c * 8);
            cpa16(base + 3 * ATT_TILE + doff, Vlbh + (size_t)r * NSEQ + kt + c * 8);
        }
        CP_COMMIT();
    };

    const int ntile = klend >> 6;
    load_tile(0, 0);
    if (ntile > 1) load_tile(64, 1);

    for (int t = 0; t < ntile; t++) {
        const int s = t % 3;
        __syncthreads();                      // frees buffer (t+2)%3 (tile t-1 done)
        if (t + 2 < ntile) { load_tile((t + 2) << 6, (t + 2) % 3); CP_WAIT2(); }
        else if (t + 1 < ntile) { CP_WAIT1(); }
        else { CP_WAIT0(); }

        const uint32_t sbK = smem_u + s * ATT_STAGE;
        const uint32_t sbV = sbK + 2 * ATT_TILE;

        float sc[8][4] = {};
        #pragma unroll
        for (int kk = 0; kk < 4; kk++) {
            #pragma unroll
            for (int j = 0; j < 4; j++) {
                uint32_t kd = sbK + (uint32_t)((j * 16 + bN) * KSTR * 2 + kk * 32 + bHalf * 16);
                uint32_t t0[4], t1[4];
                ldm_x4(t0, kd);
                ldm_x4(t1, kd + ATT_TILE);
                uint32_t kb0[2] = { t0[0], t0[1] }, kb1[2] = { t0[2], t0[3] };
                uint32_t kl0[2] = { t1[0], t1[1] }, kl1[2] = { t1[2], t1[3] };
                mma_bf16(sc[2 * j],     qhf[kk], kb0);
                mma_bf16(sc[2 * j],     qhf[kk], kl0);
                mma_bf16(sc[2 * j],     qlf[kk], kb0);
                mma_bf16(sc[2 * j + 1], qhf[kk], kb1);
                mma_bf16(sc[2 * j + 1], qhf[kk], kl1);
                mma_bf16(sc[2 * j + 1], qlf[kk], kb1);
            }
        }

        float mt0 = -1e30f, mt1 = -1e30f;
        #pragma unroll
        for (int nt = 0; nt < 8; nt++) {
            mt0 = fmaxf(mt0, fmaxf(sc[nt][0], sc[nt][1]));
            mt1 = fmaxf(mt1, fmaxf(sc[nt][2], sc[nt][3]));
        }
        mt0 = fmaxf(mt0, __shfl_xor_sync(0xffffffffu, mt0, 1));
        mt0 = fmaxf(mt0, __shfl_xor_sync(0xffffffffu, mt0, 2));
        mt1 = fmaxf(mt1, __shfl_xor_sync(0xffffffffu, mt1, 1));
        mt1 = fmaxf(mt1, __shfl_xor_sync(0xffffffffu, mt1, 2));

        float mn0 = fmaxf(m0, mt0), mn1 = fmaxf(m1, mt1);
        float c0 = ex2f(m0 - mn0), c1 = ex2f(m1 - mn1);
        m0 = mn0; m1 = mn1;
        l0 *= c0; l1 *= c1;

        uint32_t pha[4][4], pla[4][4];
        #pragma unroll
        for (int nt = 0; nt < 8; nt++) {
            float p0 = ex2f(sc[nt][0] - m0);
            float p1 = ex2f(sc[nt][1] - m0);
            float p2 = ex2f(sc[nt][2] - m1);
            float p3 = ex2f(sc[nt][3] - m1);
            l0 += p0 + p1;
            l1 += p2 + p3;
            int kk = nt >> 1, hf = nt & 1;
            pha[kk][hf * 2 + 0] = pack2(p0, p1);
            pha[kk][hf * 2 + 1] = pack2(p2, p3);
            pla[kk][hf * 2 + 0] = pack2lo(p0, p1);
            pla[kk][hf * 2 + 1] = pack2lo(p2, p3);
        }

        #pragma unroll
        for (int nt = 0; nt < 8; nt++) {
            o[nt][0] *= c0; o[nt][1] *= c0;
            o[nt][2] *= c1; o[nt][3] *= c1;
        }

        #pragma unroll
        for (int kk = 0; kk < 4; kk++) {
            #pragma unroll
            for (int j = 0; j < 4; j++) {
                uint32_t vd = sbV + (uint32_t)((j * 16 + bN) * KSTR * 2 + kk * 32 + bHalf * 16);
                uint32_t t0[4], t1[4];
                ldm_x4(t0, vd);
                ldm_x4(t1, vd + ATT_TILE);
                uint32_t vb0[2] = { t0[0], t0[1] }, vb1[2] = { t0[2], t0[3] };
                uint32_t vl0[2] = { t1[0], t1[1] }, vl1[2] = { t1[2], t1[3] };
                mma_bf16(o[2 * j],     pha[kk], vb0);
                mma_bf16(o[2 * j],     pha[kk], vl0);
                mma_bf16(o[2 * j],     pla[kk], vb0);
                mma_bf16(o[2 * j + 1], pha[kk], vb1);
                mma_bf16(o[2 * j + 1], pha[kk], vl1);
                mma_bf16(o[2 * j + 1], pla[kk], vb1);
            }
        }
    }

    l0 += __shfl_xor_sync(0xffffffffu, l0, 1);
    l0 += __shfl_xor_sync(0xffffffffu, l0, 2);
    l1 += __shfl_xor_sync(0xffffffffu, l1, 1);
    l1 += __shfl_xor_sync(0xffffffffu, l1, 2);
    const float inv0 = 1.0f / l0, inv1 = 1.0f / l1;

    size_t off0 = ((size_t)(b * NSEQ + r0)) * DIM + h * HD;
    size_t off1 = ((size_t)(b * NSEQ + r0 + 8)) * DIM + h * HD;
    #pragma unroll
    for (int nt = 0; nt < 8; nt++) {
        int col = nt * 8 + 2 * q;
        float a0 = o[nt][0] * inv0, a1 = o[nt][1] * inv0;
        float b0 = o[nt][2] * inv1, b1 = o[nt][3] * inv1;
        *(uint32_t*)(Oh + off0 + col) = pack2(a0, a1);
        *(uint32_t*)(Ol + off0 + col) = pack2lo(a0, a1);
        *(uint32_t*)(Oh + off1 + col) = pack2(b0, b1);
        *(uint32_t*)(Ol + off1 + col) = pack2lo(b0, b1);
    }
}

// ------------------------------------------------------------------- launch
__global__ void __launch_bounds__(256) split_o_kernel(
    const float* __restrict__ src, bf16* __restrict__ hi,
    bf16* __restrict__ lo, int n4)
{
    int i = blockIdx.x * blockDim.x + threadIdx.x;
    if (i >= n4) return;
    float4 v = *(const float4*)(src + (size_t)i * 4);
    *(uint32_t*)(hi + (size_t)i * 4)     = pack2(v.x, v.y);
    *(uint32_t*)(hi + (size_t)i * 4 + 2) = pack2(v.z, v.w);
    *(uint32_t*)(lo + (size_t)i * 4)     = pack2lo(v.x, v.y);
    *(uint32_t*)(lo + (size_t)i * 4 + 2) = pack2lo(v.z, v.w);
}

extern "C" void kernel_launch(void* const* d_in, const int* in_sizes, int n_in,
                              void* d_out, int out_size)
{
    const float* x       = (const float*)d_in[0];
    const float* Wqkv    = (const float*)d_in[1];
    const float* Aqkv    = (const float*)d_in[2];
    const float* Bqkv    = (const float*)d_in[3];
    const float* Wproj   = (const float*)d_in[4];
    const float* Aproj   = (const float*)d_in[5];
    const float* Bproj   = (const float*)d_in[6];
    const int*   experts = (const int*)d_in[7];
    float*       out     = (float*)d_out;

    int estride = (in_sizes[7] >= 2 * NCHUNKS) ? 2 : 1;

    bf16 *xh, *xl, *oh, *ol, *wqh, *wql, *wph, *wpl;
    bf16 *bqh, *bql, *bph, *bpl, *aqh, *aql, *aph, *apl, *hh, *hl;
    bf16 *qah, *qal, *kah, *kal, *vth, *vtl;
    cudaGetSymbolAddress((void**)&xh,  g_xh);  cudaGetSymbolAddress((void**)&xl,  g_xl);
    cudaGetSymbolAddress((void**)&oh,  g_oh);  cudaGetSymbolAddress((void**)&ol,  g_ol);
    cudaGetSymbolAddress((void**)&wqh, g_wqh); cudaGetSymbolAddress((void**)&wql, g_wql);
    cudaGetSymbolAddress((void**)&wph, g_wph); cudaGetSymbolAddress((void**)&wpl, g_wpl);
    cudaGetSymbolAddress((void**)&bqh, g_bqh); cudaGetSymbolAddress((void**)&bql, g_bql);
    cudaGetSymbolAddress((void**)&bph, g_bph); cudaGetSymbolAddress((void**)&bpl, g_bpl);
    cudaGetSymbolAddress((void**)&aqh, g_aqh); cudaGetSymbolAddress((void**)&aql, g_aql);
    cudaGetSymbolAddress((void**)&aph, g_aph); cudaGetSymbolAddress((void**)&apl, g_apl);
    cudaGetSymbolAddress((void**)&hh,  g_hh);  cudaGetSymbolAddress((void**)&hl,  g_hl);
    cudaGetSymbolAddress((void**)&qah, g_qah); cudaGetSymbolAddress((void**)&qal, g_qal);
    cudaGetSymbolAddress((void**)&kah, g_kah); cudaGetSymbolAddress((void**)&kal, g_kal);
    cudaGetSymbolAddress((void**)&vth, g_vth); cudaGetSymbolAddress((void**)&vtl, g_vtl);

    cudaFuncSetAttribute(qkv_gemm, cudaFuncAttributeMaxDynamicSharedMemorySize, MMG_SMEM);
    cudaFuncSetAttribute(proj_gemm, cudaFuncAttributeMaxDynamicSharedMemorySize, P_SMEM);
    cudaFuncSetAttribute(lora_mma, cudaFuncAttributeMaxDynamicSharedMemorySize, L2_SMEM);
    cudaFuncSetAttribute(attn_mma, cudaFuncAttributeMaxDynamicSharedMemorySize, ATT_SMEM);

    // 0) fused split of all fp32 operands into bf16 hi/lo (one launch)
    {
        SplitArgs sa;
        sa.src[0] = x;     sa.hi[0] = xh;  sa.lo[0] = xl;
        sa.src[1] = Wqkv;  sa.hi[1] = wqh; sa.lo[1] = wql;
        sa.src[2] = Bqkv;  sa.hi[2] = bqh; sa.lo[2] = bql;
        sa.src[3] = Wproj; sa.hi[3] = wph; sa.lo[3] = wpl;
        sa.src[4] = Bproj; sa.hi[4] = bph; sa.lo[4] = bpl;
        sa.src[5] = Aqkv;  sa.hi[5] = aqh; sa.lo[5] = aql;
        sa.src[6] = Aproj; sa.hi[6] = aph; sa.lo[6] = apl;
        split_all<<<(C4_6 + 255) / 256, 256>>>(sa);
    }

    // 1) H = split(LSCALE * x @ Aqkv[e]^T)
    lora_mma<<<TOKENS / 64, 256, L2_SMEM>>>(xh, xl, aqh, aql, hh, hl, experts, estride);

    // 2) QKV GEMM with fused attention-operand epilogue
    {
        dim3 grid(QKV_DIM / 128, TOKENS / 128);
        qkv_gemm<<<grid, 256, MMG_SMEM>>>(xh, xl, wqh, wql, hh, hl, bqh, bql,
                                          qah, qal, kah, kal, vth, vtl,
                                          experts, estride);
    }

    // 3) tensor-core chunked block-causal attention (writes split o)
    {
        dim3 grid(CHUNK / 128, BB * HEADS, NCHUNKS);
        attn_mma<<<grid, 256, ATT_SMEM>>>(qah, qal, kah, kal, vth, vtl, oh, ol);
    }

    // 4) H2 = split(LSCALE * o @ Aproj[e]^T)
    lora_mma<<<TOKENS / 64, 256, L2_SMEM>>>(oh, ol, aph, apl, hh, hl, experts, estride);

    // 5) out = o @ Wproj^T + H2 @ Bproj[e]^T (128x64 tiles)
    {
        dim3 grid(DIM / 64, TOKENS / 128);
        proj_gemm<<<grid, 256, P_SMEM>>>(oh, ol, wph, wpl, hh, hl, bph, bpl,
                                         out, experts, estride);
    }
}